// round 11
// baseline (speedup 1.0000x reference)
#include <cuda_runtime.h>
#include <cuda_fp16.h>
#include <cstdint>

// Bilinear attention, B=16, T=D=1024:
//   qW = query @ W ; logits = qW @ keys^T + mask ; score = softmax(logits) ; ctx = score @ values
// GEMMs via mma.sync.m16n8k16 fp16, error-compensated split, fp32 accumulate.
// Operands pre-split into f16 hi/lo planes in GMEM (one cheap pass each);
// GEMM producers are pure LDG.128 -> STS.128 copies (zero ALU), register-staged
// one full chunk ahead exactly like the best-so-far kernel. Same SMEM plane
// layout / frag LDS / MMA order => numerics identical to R8.
// 128 thr/CTA, warp tile 64x64, 2-slot ring, one barrier per 16-k chunk.
// TERMS: 3 = Ahi*Bhi+Ahi*Blo+Alo*Bhi (logit path) ; 1 = Ahi*Bhi (post-softmax)

#define NDIM 1024

// Static plane scratch (allocation-guard safe)
__device__ __half g_qh[16777216],  g_ql[16777216];    // query hi/lo
__device__ __half g_kh[16777216],  g_kl[16777216];    // keys hi/lo
__device__ __half g_qWh[16777216], g_qWl[16777216];   // qW hi/lo (GEMM1 out)
__device__ __half g_Wth[1048576],  g_Wtl[1048576];    // W^T hi/lo
__device__ __half g_valh[16777216];                   // values^T hi
__device__ __half g_sch[16777216];                    // score hi (softmax out)

// ---- helpers -------------------------------------------------------------
static __device__ __forceinline__ uint32_t pack_h2(float e0, float e1) {
    uint32_t r;   // r.lo = f16(e0), r.hi = f16(e1)
    asm("cvt.rn.f16x2.f32 %0, %1, %2;" : "=r"(r) : "f"(e1), "f"(e0));
    return r;
}
static __device__ __forceinline__ void split_pair(float x, float y, uint32_t& h, uint32_t& l) {
    h = pack_h2(x, y);
    __half2 hh = *reinterpret_cast<__half2*>(&h);
    l = pack_h2(x - __low2float(hh), y - __high2float(hh));
}
static __device__ __forceinline__ void mma16(float* d, const uint32_t* a, const uint32_t* b) {
    asm volatile(
        "mma.sync.aligned.m16n8k16.row.col.f32.f16.f16.f32 "
        "{%0,%1,%2,%3}, {%4,%5,%6,%7}, {%8,%9}, {%0,%1,%2,%3};"
        : "+f"(d[0]), "+f"(d[1]), "+f"(d[2]), "+f"(d[3])
        : "r"(a[0]), "r"(a[1]), "r"(a[2]), "r"(a[3]), "r"(b[0]), "r"(b[1]));
}

// ---- SMEM plane layout (identical to R8) ----------------------------------
// Row = 16 halves data + 8 halves pad = 48 bytes (conflict-free frag LDS + STS).
// Planes per slot: A-hi, A-lo, B-hi, B-lo, each 128 rows x 48B = 6144 B.
#define ROWB 48
#define PLANE 6144

template<int TERMS, int EPI>   // EPI: 0 = f32 out, 1 = f32 + mask, 2 = f16 hi/lo planes out
__global__ __launch_bounds__(128) void gemm_plane_kernel(
    const __half* __restrict__ Ah, const __half* __restrict__ Al,
    const __half* __restrict__ Bh, const __half* __restrict__ Bl,
    float* __restrict__ C, __half* __restrict__ Ch, __half* __restrict__ Cl,
    const float* __restrict__ mask, size_t sA, size_t sB, size_t sC)
{
    constexpr int AHO = 0;
    constexpr int ALO = PLANE;
    constexpr int BHO = (TERMS == 3) ? 2 * PLANE : PLANE;
    constexpr int BLO = 3 * PLANE;
    constexpr int SLOT = (TERMS == 3) ? 4 * PLANE : 2 * PLANE;

    extern __shared__ __align__(16) char smem[];
    const int tid = threadIdx.x, wid = tid >> 5, lid = tid & 31;
    const int g = lid >> 2, tg = lid & 3;                  // mma group / thread-in-group
    const int wm = (wid >> 1) * 64, wn = (wid & 1) * 64;   // 2x2 warp grid, 64x64 tiles
    const int M0 = blockIdx.y * 128, N0 = blockIdx.x * 128;
    const size_t b = blockIdx.z;
    const float* mp = (EPI == 1) ? (mask + b * 1024) : nullptr;

    // producer: thread tid owns row tid of both the A rows (M0+tid) and B rows (N0+tid)
    const __half* Agh = Ah + b * sA + (size_t)(M0 + tid) * NDIM;
    const __half* Bgh = Bh + b * sB + (size_t)(N0 + tid) * NDIM;
    const __half* Agl = (TERMS == 3) ? (Al + b * sA + (size_t)(M0 + tid) * NDIM) : nullptr;
    const __half* Bgl = (TERMS == 3) ? (Bl + b * sB + (size_t)(N0 + tid) * NDIM) : nullptr;

    float acc[4][8][4];
    #pragma unroll
    for (int mi = 0; mi < 4; mi++)
        #pragma unroll
        for (int ni = 0; ni < 8; ni++)
            #pragma unroll
            for (int v = 0; v < 4; v++) acc[mi][ni][v] = 0.0f;

    uint4 bAh[2], bBh[2], bAl[2], bBl[2];

    auto ldg = [&](int c) {
        const int k0 = c << 4;
        bAh[0] = *(const uint4*)(Agh + k0); bAh[1] = *(const uint4*)(Agh + k0 + 8);
        bBh[0] = *(const uint4*)(Bgh + k0); bBh[1] = *(const uint4*)(Bgh + k0 + 8);
        if (TERMS == 3) {
            bAl[0] = *(const uint4*)(Agl + k0); bAl[1] = *(const uint4*)(Agl + k0 + 8);
            bBl[0] = *(const uint4*)(Bgl + k0); bBl[1] = *(const uint4*)(Bgl + k0 + 8);
        }
    };

    auto sts = [&](int slot) {
        char* base = smem + slot * SLOT + tid * ROWB;
        *(uint4*)(base + AHO)      = bAh[0];
        *(uint4*)(base + AHO + 16) = bAh[1];
        *(uint4*)(base + BHO)      = bBh[0];
        *(uint4*)(base + BHO + 16) = bBh[1];
        if (TERMS == 3) {
            *(uint4*)(base + ALO)      = bAl[0];
            *(uint4*)(base + ALO + 16) = bAl[1];
            *(uint4*)(base + BLO)      = bBl[0];
            *(uint4*)(base + BLO + 16) = bBl[1];
        }
    };

    auto frag_mma = [&](int slot) {
        const char* base = smem + slot * SLOT;
        uint32_t bh[8][2], bl[8][2];
        #pragma unroll
        for (int ni = 0; ni < 8; ni++) {
            const int n0 = (wn + ni * 8 + g) * ROWB + tg * 4;
            bh[ni][0] = *(const uint32_t*)(base + BHO + n0);
            bh[ni][1] = *(const uint32_t*)(base + BHO + n0 + 16);
            if (TERMS == 3) {
                bl[ni][0] = *(const uint32_t*)(base + BLO + n0);
                bl[ni][1] = *(const uint32_t*)(base + BLO + n0 + 16);
            }
        }
        #pragma unroll
        for (int mi = 0; mi < 4; mi++) {
            const int r0 = (wm + mi * 16 + g) * ROWB + tg * 4;
            const int r1 = r0 + 8 * ROWB;
            uint32_t ah[4], al[4];
            ah[0] = *(const uint32_t*)(base + AHO + r0);
            ah[1] = *(const uint32_t*)(base + AHO + r1);
            ah[2] = *(const uint32_t*)(base + AHO + r0 + 16);
            ah[3] = *(const uint32_t*)(base + AHO + r1 + 16);
            if (TERMS == 3) {
                al[0] = *(const uint32_t*)(base + ALO + r0);
                al[1] = *(const uint32_t*)(base + ALO + r1);
                al[2] = *(const uint32_t*)(base + ALO + r0 + 16);
                al[3] = *(const uint32_t*)(base + ALO + r1 + 16);
            }
            #pragma unroll
            for (int ni = 0; ni < 8; ni++) {
                mma16(acc[mi][ni], ah, bh[ni]);
                if (TERMS == 3) {
                    mma16(acc[mi][ni], ah, bl[ni]);
                    mma16(acc[mi][ni], al, bh[ni]);
                }
            }
        }
    };

    // prologue: fill slot 0   (R8 cadence: ldg one chunk ahead, sts after mma)
    ldg(0);
    sts(0);
    __syncthreads();

    for (int c = 0; c < 64; c++) {
        if (c + 1 < 64) ldg(c + 1);       // in flight during MMA phase
        frag_mma(c & 1);
        if (c + 1 < 64) sts((c + 1) & 1); // slot drained in iter c-1 (bar'ed)
        __syncthreads();
    }

    // epilogue: d0,d1 at (g, 2tg..2tg+1), d2,d3 at (g+8, ...)
    #pragma unroll
    for (int mi = 0; mi < 4; mi++) {
        #pragma unroll
        for (int ni = 0; ni < 8; ni++) {
            const int r0 = M0 + wm + mi * 16 + g;
            const int cc = N0 + wn + ni * 8 + 2 * tg;
            float2 v0 = make_float2(acc[mi][ni][0], acc[mi][ni][1]);
            float2 v1 = make_float2(acc[mi][ni][2], acc[mi][ni][3]);
            if (EPI == 2) {
                uint32_t h0, l0, h1, l1;
                split_pair(v0.x, v0.y, h0, l0);
                split_pair(v1.x, v1.y, h1, l1);
                *(uint32_t*)(Ch + (size_t)r0 * NDIM + cc)       = h0;
                *(uint32_t*)(Cl + (size_t)r0 * NDIM + cc)       = l0;
                *(uint32_t*)(Ch + (size_t)(r0 + 8) * NDIM + cc) = h1;
                *(uint32_t*)(Cl + (size_t)(r0 + 8) * NDIM + cc) = l1;
            } else {
                if (EPI == 1) {
                    const float m0v = mp[cc], m1v = mp[cc + 1];
                    v0.x += m0v; v0.y += m1v;
                    v1.x += m0v; v1.y += m1v;
                }
                float* Cb = C + b * sC;
                *(float2*)(Cb + (size_t)r0 * NDIM + cc)       = v0;
                *(float2*)(Cb + (size_t)(r0 + 8) * NDIM + cc) = v1;
            }
        }
    }
}

// elementwise split: f32 -> f16 hi + f16 lo planes (float4 per thread)
__global__ __launch_bounds__(256) void split_kernel(const float4* __restrict__ src,
                                                    __half* __restrict__ dh,
                                                    __half* __restrict__ dl)
{
    const size_t i = (size_t)blockIdx.x * blockDim.x + threadIdx.x;
    float4 v = src[i];
    uint32_t h0, l0, h1, l1;
    split_pair(v.x, v.y, h0, l0);
    split_pair(v.z, v.w, h1, l1);
    *(uint2*)(dh + 4 * i) = make_uint2(h0, h1);
    *(uint2*)(dl + 4 * i) = make_uint2(l0, l1);
}

// 1024x1024 transpose + split to f16 planes (per blockIdx.z slice), block (32,8)
template<bool LO>
__global__ __launch_bounds__(256) void transpose_split_kernel(
    const float* __restrict__ src, __half* __restrict__ dh, __half* __restrict__ dl)
{
    __shared__ float t[32][33];
    const size_t b = blockIdx.z;
    src += b * 1048576ull;
    dh += b * 1048576ull;
    if (LO) dl += b * 1048576ull;
    const int bx = blockIdx.x * 32, by = blockIdx.y * 32;
    const int x = threadIdx.x, y4 = threadIdx.y * 4;
    #pragma unroll
    for (int i = 0; i < 4; i++)
        t[y4 + i][x] = src[(size_t)(by + y4 + i) * 1024 + bx + x];
    __syncthreads();
    #pragma unroll
    for (int i = 0; i < 4; i++) {
        const float v = t[x][y4 + i];
        const size_t o = (size_t)(bx + y4 + i) * 1024 + by + x;
        const __half h = __float2half_rn(v);
        dh[o] = h;
        if (LO) dl[o] = __float2half_rn(v - __half2float(h));
    }
}

// In-place row softmax, row length 1024; also emits f16 score plane
__global__ __launch_bounds__(256) void softmax_kernel(float* __restrict__ S,
                                                      __half* __restrict__ Sh)
{
    __shared__ float red[8];
    size_t row = blockIdx.x;
    float4* p = reinterpret_cast<float4*>(S + row * 1024);
    int t = threadIdx.x;

    float4 v = p[t];
    float m = fmaxf(fmaxf(v.x, v.y), fmaxf(v.z, v.w));
    #pragma unroll
    for (int o = 16; o; o >>= 1) m = fmaxf(m, __shfl_xor_sync(0xffffffffu, m, o));
    if ((t & 31) == 0) red[t >> 5] = m;
    __syncthreads();
    m = red[0];
    #pragma unroll
    for (int i = 1; i < 8; i++) m = fmaxf(m, red[i]);

    v.x = expf(v.x - m); v.y = expf(v.y - m);
    v.z = expf(v.z - m); v.w = expf(v.w - m);
    float s = v.x + v.y + v.z + v.w;
    #pragma unroll
    for (int o = 16; o; o >>= 1) s += __shfl_xor_sync(0xffffffffu, s, o);
    __syncthreads();
    if ((t & 31) == 0) red[t >> 5] = s;
    __syncthreads();
    s = red[0];
    #pragma unroll
    for (int i = 1; i < 8; i++) s += red[i];

    float inv = 1.0f / s;
    v.x *= inv; v.y *= inv; v.z *= inv; v.w *= inv;
    p[t] = v;

    uint32_t h0 = pack_h2(v.x, v.y), h1 = pack_h2(v.z, v.w);
    *(uint2*)(Sh + row * 1024 + 4 * t) = make_uint2(h0, h1);
}

extern "C" void kernel_launch(void* const* d_in, const int* in_sizes, int n_in,
                              void* d_out, int out_size)
{
    (void)in_sizes; (void)n_in; (void)out_size;
    const float* query  = (const float*)d_in[0];   // [16,1024,1024]
    const float* keys   = (const float*)d_in[1];   // [16,1024,1024]
    const float* values = (const float*)d_in[2];   // [16,1024,1024]
    const float* W      = (const float*)d_in[3];   // [1024,1024]
    const float* mask   = (const float*)d_in[4];   // [16,1024]

    float* score = (float*)d_out;                        // [16,1024,1024]
    float* ctx   = score + (size_t)16 * 1024 * 1024;     // [16,1024,1024]

    const int SMEM3 = 2 * 4 * PLANE;   // 49152
    const int SMEM1 = 2 * 2 * PLANE;   // 24576
    cudaFuncSetAttribute(gemm_plane_kernel<3, 2>,
                         cudaFuncAttributeMaxDynamicSharedMemorySize, SMEM3);
    cudaFuncSetAttribute(gemm_plane_kernel<3, 1>,
                         cudaFuncAttributeMaxDynamicSharedMemorySize, SMEM3);
    cudaFuncSetAttribute(gemm_plane_kernel<1, 0>,
                         cudaFuncAttributeMaxDynamicSharedMemorySize, SMEM1);

    __half *qh, *ql, *kh, *kl, *qWh, *qWl, *Wth, *Wtl, *valh, *sch;
    cudaGetSymbolAddress((void**)&qh,   g_qh);
    cudaGetSymbolAddress((void**)&ql,   g_ql);
    cudaGetSymbolAddress((void**)&kh,   g_kh);
    cudaGetSymbolAddress((void**)&kl,   g_kl);
    cudaGetSymbolAddress((void**)&qWh,  g_qWh);
    cudaGetSymbolAddress((void**)&qWl,  g_qWl);
    cudaGetSymbolAddress((void**)&Wth,  g_Wth);
    cudaGetSymbolAddress((void**)&Wtl,  g_Wtl);
    cudaGetSymbolAddress((void**)&valh, g_valh);
    cudaGetSymbolAddress((void**)&sch,  g_sch);

    // Pre-split operands into f16 planes (bandwidth-bound, ~65 us total)
    split_kernel<<<16384, 256>>>((const float4*)query, qh, ql);
    split_kernel<<<16384, 256>>>((const float4*)keys,  kh, kl);
    transpose_split_kernel<true><<<dim3(32, 32, 1),  dim3(32, 8)>>>(W, Wth, Wtl);
    transpose_split_kernel<false><<<dim3(32, 32, 16), dim3(32, 8)>>>(values, valh, nullptr);

    // qW = query @ W  (NT, 3-term) -> qW hi/lo planes directly
    gemm_plane_kernel<3, 2><<<dim3(8, 128, 1), 128, SMEM3>>>(
        qh, ql, Wth, Wtl, nullptr, qWh, qWl, nullptr, 0, 0, 0);

    // logits = qW @ keys^T + mask -> score (f32, d_out)
    gemm_plane_kernel<3, 1><<<dim3(8, 8, 16), 128, SMEM3>>>(
        qWh, qWl, kh, kl, score, nullptr, nullptr, mask,
        1048576, 1048576, 1048576);

    // softmax in place; emit f16 score plane
    softmax_kernel<<<16384, 256>>>(score, sch);

    // ctx = score @ values (NT on values^T), 1-term fp16
    gemm_plane_kernel<1, 0><<<dim3(8, 8, 16), 128, SMEM1>>>(
        sch, nullptr, valh, nullptr, ctx, nullptr, nullptr, nullptr,
        1048576, 1048576, 1048576);
}

// round 12
// speedup vs baseline: 1.4198x; 1.4198x over previous
#include <cuda_runtime.h>
#include <cuda_fp16.h>
#include <cstdint>

// Bilinear attention, B=16, T=D=1024.
// R8's proven register-staged GEMM loop, with redundant work removed around it:
//  - GEMM1 (query@W, 3-term) epilogue emits qW as f16 hi/lo planes (split once)
//  - GEMM2 (qW@keys^T, 3-term) A-side producer = pure copy; B-side = R8 f32 split
//  - GEMM3 (score@values, 1-term) fully plane-fed (f16 score from softmax, f16 valT)
// Numerics identical to R8. 128 thr/CTA, warp tile 64x64, 2-slot ring.

#define NDIM 1024

// Static scratch (allocation-guard safe)
__device__ float  g_Wt[1048576];       // W^T (f32)
__device__ __half g_qWh[16777216];     // qW hi plane
__device__ __half g_qWl[16777216];     // qW lo plane
__device__ __half g_valh[16777216];    // values^T hi plane
__device__ __half g_sch[16777216];     // score hi plane (softmax out)

// ---- helpers -------------------------------------------------------------
static __device__ __forceinline__ uint32_t pack_h2(float e0, float e1) {
    uint32_t r;   // r.lo = f16(e0), r.hi = f16(e1)
    asm("cvt.rn.f16x2.f32 %0, %1, %2;" : "=r"(r) : "f"(e1), "f"(e0));
    return r;
}
static __device__ __forceinline__ void split_pair(float x, float y, uint32_t& h, uint32_t& l) {
    h = pack_h2(x, y);
    __half2 hh = *reinterpret_cast<__half2*>(&h);
    l = pack_h2(x - __low2float(hh), y - __high2float(hh));
}
static __device__ __forceinline__ void mma16(float* d, const uint32_t* a, const uint32_t* b) {
    asm volatile(
        "mma.sync.aligned.m16n8k16.row.col.f32.f16.f16.f32 "
        "{%0,%1,%2,%3}, {%4,%5,%6,%7}, {%8,%9}, {%0,%1,%2,%3};"
        : "+f"(d[0]), "+f"(d[1]), "+f"(d[2]), "+f"(d[3])
        : "r"(a[0]), "r"(a[1]), "r"(a[2]), "r"(a[3]), "r"(b[0]), "r"(b[1]));
}

// ---- SMEM plane layout (R8) -----------------------------------------------
// Row = 16 halves data + 8 halves pad = 48 B (conflict-free frag LDS + STS).
#define ROWB 48
#define PLANE 6144

// TERMS: 3 = Ahi*Bhi+Ahi*Blo+Alo*Bhi ; 1 = Ahi*Bhi
// APL/BPL: operand arrives as pre-split f16 planes (pure-copy producer)
// EPI: 0 = f32 out, 1 = f32 + mask, 2 = f16 hi/lo planes out
template<int TERMS, bool APL, bool BPL, int EPI>
__global__ __launch_bounds__(128) void gemm_k(
    const float* __restrict__ Af, const __half* __restrict__ Aph,
    const __half* __restrict__ Apl,
    const float* __restrict__ Bf, const __half* __restrict__ Bph,
    float* __restrict__ C, __half* __restrict__ Ch, __half* __restrict__ Cl,
    const float* __restrict__ mask, size_t sA, size_t sB, size_t sC)
{
    constexpr int AHO = 0;
    constexpr int ALO = PLANE;                               // only if TERMS==3
    constexpr int BHO = (TERMS == 3) ? 2 * PLANE : PLANE;
    constexpr int BLO = 3 * PLANE;
    constexpr int SLOT = (TERMS == 3) ? 4 * PLANE : 2 * PLANE;

    extern __shared__ __align__(16) char smem[];
    const int tid = threadIdx.x, wid = tid >> 5, lid = tid & 31;
    const int g = lid >> 2, tg = lid & 3;                  // mma group / thread-in-group
    const int wm = (wid >> 1) * 64, wn = (wid & 1) * 64;   // 2x2 warp grid, 64x64 tiles
    const int M0 = blockIdx.y * 128, N0 = blockIdx.x * 128;
    const size_t b = blockIdx.z;
    const float* mp = (EPI == 1) ? (mask + b * 1024) : nullptr;

    // producer geometry (R8): r = row-in-pass (0..31, +32/pass), q = k-quarter
    const int r = tid >> 2, q = tid & 3;
    const float*  Agf = APL ? nullptr : (Af  + b * sA + (size_t)(M0 + r) * NDIM + 4 * q);
    const __half* Agh = APL ? (Aph + b * sA + (size_t)(M0 + r) * NDIM + 4 * q) : nullptr;
    const __half* Agl = (APL && TERMS == 3)
                        ? (Apl + b * sA + (size_t)(M0 + r) * NDIM + 4 * q) : nullptr;
    const float*  Bgf = BPL ? nullptr : (Bf  + b * sB + (size_t)(N0 + r) * NDIM + 4 * q);
    const __half* Bgh = BPL ? (Bph + b * sB + (size_t)(N0 + r) * NDIM + 4 * q) : nullptr;

    float acc[4][8][4];
    #pragma unroll
    for (int mi = 0; mi < 4; mi++)
        #pragma unroll
        for (int ni = 0; ni < 8; ni++)
            #pragma unroll
            for (int v = 0; v < 4; v++) acc[mi][ni][v] = 0.0f;

    float4 bufAf[4], bufBf[4];
    uint2  bufAh[4], bufAl[4], bufBh[4];

    auto ldg = [&](int c) {
        const int k0 = c << 4;
        #pragma unroll
        for (int p = 0; p < 4; p++) {
            if (APL) {
                bufAh[p] = *(const uint2*)(Agh + (size_t)32 * p * NDIM + k0);
                if (TERMS == 3)
                    bufAl[p] = *(const uint2*)(Agl + (size_t)32 * p * NDIM + k0);
            } else {
                bufAf[p] = *(const float4*)(Agf + (size_t)32 * p * NDIM + k0);
            }
            if (BPL) bufBh[p] = *(const uint2*)(Bgh + (size_t)32 * p * NDIM + k0);
            else     bufBf[p] = *(const float4*)(Bgf + (size_t)32 * p * NDIM + k0);
        }
    };

    auto sts = [&](int slot) {
        char* base = smem + slot * SLOT;
        #pragma unroll
        for (int p = 0; p < 4; p++) {
            const int ro = (r + 32 * p) * ROWB + q * 8;
            if (APL) {
                *(uint2*)(base + AHO + ro) = bufAh[p];
                if (TERMS == 3) *(uint2*)(base + ALO + ro) = bufAl[p];
            } else {
                uint32_t h0, h1, l0, l1;
                if (TERMS == 3) {
                    split_pair(bufAf[p].x, bufAf[p].y, h0, l0);
                    split_pair(bufAf[p].z, bufAf[p].w, h1, l1);
                    *(uint2*)(base + AHO + ro) = make_uint2(h0, h1);
                    *(uint2*)(base + ALO + ro) = make_uint2(l0, l1);
                } else {
                    h0 = pack_h2(bufAf[p].x, bufAf[p].y);
                    h1 = pack_h2(bufAf[p].z, bufAf[p].w);
                    *(uint2*)(base + AHO + ro) = make_uint2(h0, h1);
                }
            }
            if (BPL) {
                *(uint2*)(base + BHO + ro) = bufBh[p];
            } else {
                uint32_t h0, h1, l0, l1;
                if (TERMS == 3) {
                    split_pair(bufBf[p].x, bufBf[p].y, h0, l0);
                    split_pair(bufBf[p].z, bufBf[p].w, h1, l1);
                    *(uint2*)(base + BHO + ro) = make_uint2(h0, h1);
                    *(uint2*)(base + BLO + ro) = make_uint2(l0, l1);
                } else {
                    h0 = pack_h2(bufBf[p].x, bufBf[p].y);
                    h1 = pack_h2(bufBf[p].z, bufBf[p].w);
                    *(uint2*)(base + BHO + ro) = make_uint2(h0, h1);
                }
            }
        }
    };

    auto frag_mma = [&](int slot) {
        const char* base = smem + slot * SLOT;
        uint32_t bh[8][2], bl[8][2];
        #pragma unroll
        for (int ni = 0; ni < 8; ni++) {
            const int n0 = (wn + ni * 8 + g) * ROWB + tg * 4;
            bh[ni][0] = *(const uint32_t*)(base + BHO + n0);
            bh[ni][1] = *(const uint32_t*)(base + BHO + n0 + 16);
            if (TERMS == 3) {
                bl[ni][0] = *(const uint32_t*)(base + BLO + n0);
                bl[ni][1] = *(const uint32_t*)(base + BLO + n0 + 16);
            }
        }
        #pragma unroll
        for (int mi = 0; mi < 4; mi++) {
            const int r0 = (wm + mi * 16 + g) * ROWB + tg * 4;
            const int r1 = r0 + 8 * ROWB;
            uint32_t ah[4], al[4];
            ah[0] = *(const uint32_t*)(base + AHO + r0);
            ah[1] = *(const uint32_t*)(base + AHO + r1);
            ah[2] = *(const uint32_t*)(base + AHO + r0 + 16);
            ah[3] = *(const uint32_t*)(base + AHO + r1 + 16);
            if (TERMS == 3) {
                al[0] = *(const uint32_t*)(base + ALO + r0);
                al[1] = *(const uint32_t*)(base + ALO + r1);
                al[2] = *(const uint32_t*)(base + ALO + r0 + 16);
                al[3] = *(const uint32_t*)(base + ALO + r1 + 16);
            }
            #pragma unroll
            for (int ni = 0; ni < 8; ni++) {
                mma16(acc[mi][ni], ah, bh[ni]);
                if (TERMS == 3) {
                    mma16(acc[mi][ni], ah, bl[ni]);
                    mma16(acc[mi][ni], al, bh[ni]);
                }
            }
        }
    };

    // R8 cadence: ldg one chunk ahead; sts after mma; one bar per chunk
    ldg(0);
    sts(0);
    __syncthreads();
    for (int c = 0; c < 64; c++) {
        if (c + 1 < 64) ldg(c + 1);
        frag_mma(c & 1);
        if (c + 1 < 64) sts((c + 1) & 1);
        __syncthreads();
    }

    // epilogue
    #pragma unroll
    for (int mi = 0; mi < 4; mi++) {
        #pragma unroll
        for (int ni = 0; ni < 8; ni++) {
            const int r0 = M0 + wm + mi * 16 + g;
            const int cc = N0 + wn + ni * 8 + 2 * tg;
            float2 v0 = make_float2(acc[mi][ni][0], acc[mi][ni][1]);
            float2 v1 = make_float2(acc[mi][ni][2], acc[mi][ni][3]);
            if (EPI == 2) {
                uint32_t h0, l0, h1, l1;
                split_pair(v0.x, v0.y, h0, l0);
                split_pair(v1.x, v1.y, h1, l1);
                *(uint32_t*)(Ch + (size_t)r0 * NDIM + cc)       = h0;
                *(uint32_t*)(Cl + (size_t)r0 * NDIM + cc)       = l0;
                *(uint32_t*)(Ch + (size_t)(r0 + 8) * NDIM + cc) = h1;
                *(uint32_t*)(Cl + (size_t)(r0 + 8) * NDIM + cc) = l1;
            } else {
                if (EPI == 1) {
                    const float m0v = mp[cc], m1v = mp[cc + 1];
                    v0.x += m0v; v0.y += m1v;
                    v1.x += m0v; v1.y += m1v;
                }
                float* Cb = C + b * sC;
                *(float2*)(Cb + (size_t)r0 * NDIM + cc)       = v0;
                *(float2*)(Cb + (size_t)(r0 + 8) * NDIM + cc) = v1;
            }
        }
    }
}

// 1024x1024 f32 transpose (W), block (32,8)
__global__ __launch_bounds__(256) void transpose_kernel(const float* __restrict__ src,
                                                        float* __restrict__ dst)
{
    __shared__ float t[32][33];
    const int bx = blockIdx.x * 32, by = blockIdx.y * 32;
    const int x = threadIdx.x, y4 = threadIdx.y * 4;
    #pragma unroll
    for (int i = 0; i < 4; i++)
        t[y4 + i][x] = src[(size_t)(by + y4 + i) * 1024 + bx + x];
    __syncthreads();
    #pragma unroll
    for (int i = 0; i < 4; i++)
        dst[(size_t)(bx + y4 + i) * 1024 + by + x] = t[x][y4 + i];
}

// 1024x1024 transpose -> f16 hi plane (values), per blockIdx.z slice
__global__ __launch_bounds__(256) void transpose_h_kernel(const float* __restrict__ src,
                                                          __half* __restrict__ dh)
{
    __shared__ float t[32][33];
    const size_t b = blockIdx.z;
    src += b * 1048576ull;
    dh += b * 1048576ull;
    const int bx = blockIdx.x * 32, by = blockIdx.y * 32;
    const int x = threadIdx.x, y4 = threadIdx.y * 4;
    #pragma unroll
    for (int i = 0; i < 4; i++)
        t[y4 + i][x] = src[(size_t)(by + y4 + i) * 1024 + bx + x];
    __syncthreads();
    #pragma unroll
    for (int i = 0; i < 4; i++)
        dh[(size_t)(bx + y4 + i) * 1024 + by + x] = __float2half_rn(t[x][y4 + i]);
}

// In-place row softmax, row length 1024; emits f16 score plane
__global__ __launch_bounds__(256) void softmax_kernel(float* __restrict__ S,
                                                      __half* __restrict__ Sh)
{
    __shared__ float red[8];
    size_t row = blockIdx.x;
    float4* p = reinterpret_cast<float4*>(S + row * 1024);
    int t = threadIdx.x;

    float4 v = p[t];
    float m = fmaxf(fmaxf(v.x, v.y), fmaxf(v.z, v.w));
    #pragma unroll
    for (int o = 16; o; o >>= 1) m = fmaxf(m, __shfl_xor_sync(0xffffffffu, m, o));
    if ((t & 31) == 0) red[t >> 5] = m;
    __syncthreads();
    m = red[0];
    #pragma unroll
    for (int i = 1; i < 8; i++) m = fmaxf(m, red[i]);

    v.x = expf(v.x - m); v.y = expf(v.y - m);
    v.z = expf(v.z - m); v.w = expf(v.w - m);
    float s = v.x + v.y + v.z + v.w;
    #pragma unroll
    for (int o = 16; o; o >>= 1) s += __shfl_xor_sync(0xffffffffu, s, o);
    __syncthreads();
    if ((t & 31) == 0) red[t >> 5] = s;
    __syncthreads();
    s = red[0];
    #pragma unroll
    for (int i = 1; i < 8; i++) s += red[i];

    float inv = 1.0f / s;
    v.x *= inv; v.y *= inv; v.z *= inv; v.w *= inv;
    p[t] = v;

    uint32_t h0 = pack_h2(v.x, v.y), h1 = pack_h2(v.z, v.w);
    *(uint2*)(Sh + row * 1024 + 4 * t) = make_uint2(h0, h1);
}

extern "C" void kernel_launch(void* const* d_in, const int* in_sizes, int n_in,
                              void* d_out, int out_size)
{
    (void)in_sizes; (void)n_in; (void)out_size;
    const float* query  = (const float*)d_in[0];   // [16,1024,1024]
    const float* keys   = (const float*)d_in[1];   // [16,1024,1024]
    const float* values = (const float*)d_in[2];   // [16,1024,1024]
    const float* W      = (const float*)d_in[3];   // [1024,1024]
    const float* mask   = (const float*)d_in[4];   // [16,1024]

    float* score = (float*)d_out;                        // [16,1024,1024]
    float* ctx   = score + (size_t)16 * 1024 * 1024;     // [16,1024,1024]

    const int SMEM3 = 2 * 4 * PLANE;   // 49152
    const int SMEM1 = 2 * 2 * PLANE;   // 24576
    cudaFuncSetAttribute(gemm_k<3, false, false, 2>,
                         cudaFuncAttributeMaxDynamicSharedMemorySize, SMEM3);
    cudaFuncSetAttribute(gemm_k<3, true, false, 1>,
                         cudaFuncAttributeMaxDynamicSharedMemorySize, SMEM3);
    cudaFuncSetAttribute(gemm_k<1, true, true, 0>,
                         cudaFuncAttributeMaxDynamicSharedMemorySize, SMEM1);

    float* Wt;    cudaGetSymbolAddress((void**)&Wt,   g_Wt);
    __half *qWh, *qWl, *valh, *sch;
    cudaGetSymbolAddress((void**)&qWh,  g_qWh);
    cudaGetSymbolAddress((void**)&qWl,  g_qWl);
    cudaGetSymbolAddress((void**)&valh, g_valh);
    cudaGetSymbolAddress((void**)&sch,  g_sch);

    // Prep: W^T (f32) and values^T (f16 hi plane)
    transpose_kernel<<<dim3(32, 32, 1),  dim3(32, 8)>>>(W, Wt);
    transpose_h_kernel<<<dim3(32, 32, 16), dim3(32, 8)>>>(values, valh);

    // qW = query @ W (NT, 3-term, f32-split producers) -> qW hi/lo planes
    gemm_k<3, false, false, 2><<<dim3(8, 128, 1), 128, SMEM3>>>(
        query, nullptr, nullptr, Wt, nullptr,
        nullptr, qWh, qWl, nullptr, 0, 0, 0);

    // logits = qW @ keys^T + mask -> score (A = qW planes pure copy; B = R8 split)
    gemm_k<3, true, false, 1><<<dim3(8, 8, 16), 128, SMEM3>>>(
        nullptr, qWh, qWl, keys, nullptr,
        score, nullptr, nullptr, mask, 1048576, 1048576, 1048576);

    // softmax in place; emit f16 score plane
    softmax_kernel<<<16384, 256>>>(score, sch);

    // ctx = score @ values (both operands f16 planes, 1-term, pure-copy producer)
    gemm_k<1, true, true, 0><<<dim3(8, 8, 16), 128, SMEM1>>>(
        nullptr, sch, nullptr, nullptr, valh,
        ctx, nullptr, nullptr, nullptr, 1048576, 1048576, 1048576);
}

// round 13
// speedup vs baseline: 1.5648x; 1.1021x over previous
#include <cuda_runtime.h>
#include <cuda_fp16.h>
#include <cstdint>

// Bilinear attention, B=16, T=D=1024.
// R8 (best: 770us) with ONLY GEMM3 changed: it is fed pre-packed f16 planes
// (score plane emitted by softmax; values^T transposed straight to f16) through
// a pure LDG.128->STS.128 producer. GEMM1/GEMM2 are byte-identical to R8.
// rel_err identical (same rounding everywhere).

#define NDIM 1024

// Static scratch (allocation-guard safe)
__device__ float  g_qW[16777216];    // 16384 x 1024 (GEMM1 out, f32 as in R8)
__device__ float  g_Wt[1048576];     // W^T (f32)
__device__ __half g_valh[16777216];  // values^T f16 plane
__device__ __half g_sch[16777216];   // score f16 plane (softmax out)

// ---- helpers -------------------------------------------------------------
static __device__ __forceinline__ uint32_t pack_h2(float e0, float e1) {
    uint32_t r;   // r.lo = f16(e0), r.hi = f16(e1)
    asm("cvt.rn.f16x2.f32 %0, %1, %2;" : "=r"(r) : "f"(e1), "f"(e0));
    return r;
}
static __device__ __forceinline__ void split_pair(float x, float y, uint32_t& h, uint32_t& l) {
    h = pack_h2(x, y);
    __half2 hh = *reinterpret_cast<__half2*>(&h);
    l = pack_h2(x - __low2float(hh), y - __high2float(hh));
}
static __device__ __forceinline__ void mma16(float* d, const uint32_t* a, const uint32_t* b) {
    asm volatile(
        "mma.sync.aligned.m16n8k16.row.col.f32.f16.f16.f32 "
        "{%0,%1,%2,%3}, {%4,%5,%6,%7}, {%8,%9}, {%0,%1,%2,%3};"
        : "+f"(d[0]), "+f"(d[1]), "+f"(d[2]), "+f"(d[3])
        : "r"(a[0]), "r"(a[1]), "r"(a[2]), "r"(a[3]), "r"(b[0]), "r"(b[1]));
}

// ---- SMEM plane layout (R8) -----------------------------------------------
// Row = 16 halves data + 8 halves pad = 48 bytes (conflict-free frag LDS + STS).
#define ROWB 48
#define AH_OFF 0
#define AL_OFF 6144
#define BH_OFF 12288
#define BL_OFF 18432
#define SLOT_BYTES 24576
static constexpr int SMEM_BYTES = 2 * SLOT_BYTES;   // 49152 (3-term kernels)

// ======================= R8 kernel, verbatim (TERMS=3 users) ===============
template<bool ADDMASK, int TERMS>
__global__ __launch_bounds__(128) void gemm_fp16_kernel(
    const float* __restrict__ A, const float* __restrict__ B,
    float* __restrict__ C, const float* __restrict__ mask,
    size_t sA, size_t sB, size_t sC)
{
    extern __shared__ __align__(16) char smem[];
    const int tid = threadIdx.x, wid = tid >> 5, lid = tid & 31;
    const int g = lid >> 2, tg = lid & 3;
    const int wm = (wid >> 1) * 64, wn = (wid & 1) * 64;
    const int M0 = blockIdx.y * 128, N0 = blockIdx.x * 128;
    const size_t b = blockIdx.z;
    A += b * sA; B += b * sB; C += b * sC;
    const float* mp = ADDMASK ? (mask + b * 1024) : nullptr;

    const int r = tid >> 2, q = tid & 3;
    const float* Ag = A + (size_t)(M0 + r) * NDIM + 4 * q;
    const float* Bg = B + (size_t)(N0 + r) * NDIM + 4 * q;

    float acc[4][8][4];
    #pragma unroll
    for (int mi = 0; mi < 4; mi++)
        #pragma unroll
        for (int ni = 0; ni < 8; ni++)
            #pragma unroll
            for (int v = 0; v < 4; v++) acc[mi][ni][v] = 0.0f;

    float4 bufA[4], bufB[4];

    auto ldg = [&](int c) {
        const int k0 = c << 4;
        #pragma unroll
        for (int p = 0; p < 4; p++) {
            bufA[p] = *(const float4*)(Ag + (size_t)32 * p * NDIM + k0);
            bufB[p] = *(const float4*)(Bg + (size_t)32 * p * NDIM + k0);
        }
    };

    auto sts = [&](int slot) {
        char* base = smem + slot * SLOT_BYTES;
        #pragma unroll
        for (int p = 0; p < 4; p++) {
            const int ro = (r + 32 * p) * ROWB + q * 8;
            uint32_t h0, h1, l0, l1;
            split_pair(bufA[p].x, bufA[p].y, h0, l0);
            split_pair(bufA[p].z, bufA[p].w, h1, l1);
            *(uint2*)(base + AH_OFF + ro) = make_uint2(h0, h1);
            *(uint2*)(base + AL_OFF + ro) = make_uint2(l0, l1);
            split_pair(bufB[p].x, bufB[p].y, h0, l0);
            split_pair(bufB[p].z, bufB[p].w, h1, l1);
            *(uint2*)(base + BH_OFF + ro) = make_uint2(h0, h1);
            *(uint2*)(base + BL_OFF + ro) = make_uint2(l0, l1);
        }
    };

    auto frag_mma = [&](int slot) {
        const char* base = smem + slot * SLOT_BYTES;
        uint32_t bh[8][2], bl[8][2];
        #pragma unroll
        for (int ni = 0; ni < 8; ni++) {
            const int n0 = (wn + ni * 8 + g) * ROWB + tg * 4;
            bh[ni][0] = *(const uint32_t*)(base + BH_OFF + n0);
            bh[ni][1] = *(const uint32_t*)(base + BH_OFF + n0 + 16);
            bl[ni][0] = *(const uint32_t*)(base + BL_OFF + n0);
            bl[ni][1] = *(const uint32_t*)(base + BL_OFF + n0 + 16);
        }
        #pragma unroll
        for (int mi = 0; mi < 4; mi++) {
            const int r0 = (wm + mi * 16 + g) * ROWB + tg * 4;
            const int r1 = r0 + 8 * ROWB;
            uint32_t ah[4], al[4];
            ah[0] = *(const uint32_t*)(base + AH_OFF + r0);
            ah[1] = *(const uint32_t*)(base + AH_OFF + r1);
            ah[2] = *(const uint32_t*)(base + AH_OFF + r0 + 16);
            ah[3] = *(const uint32_t*)(base + AH_OFF + r1 + 16);
            al[0] = *(const uint32_t*)(base + AL_OFF + r0);
            al[1] = *(const uint32_t*)(base + AL_OFF + r1);
            al[2] = *(const uint32_t*)(base + AL_OFF + r0 + 16);
            al[3] = *(const uint32_t*)(base + AL_OFF + r1 + 16);
            #pragma unroll
            for (int ni = 0; ni < 8; ni++) {
                mma16(acc[mi][ni], ah, bh[ni]);
                mma16(acc[mi][ni], ah, bl[ni]);
                mma16(acc[mi][ni], al, bh[ni]);
            }
        }
    };

    ldg(0);
    sts(0);
    __syncthreads();

    for (int c = 0; c < 64; c++) {
        if (c + 1 < 64) ldg(c + 1);
        frag_mma(c & 1);
        if (c + 1 < 64) sts((c + 1) & 1);
        __syncthreads();
    }

    #pragma unroll
    for (int mi = 0; mi < 4; mi++) {
        #pragma unroll
        for (int ni = 0; ni < 8; ni++) {
            const int r0 = M0 + wm + mi * 16 + g;
            const int cc = N0 + wn + ni * 8 + 2 * tg;
            float2 v0 = make_float2(acc[mi][ni][0], acc[mi][ni][1]);
            float2 v1 = make_float2(acc[mi][ni][2], acc[mi][ni][3]);
            if (ADDMASK) {
                const float m0v = mp[cc], m1v = mp[cc + 1];
                v0.x += m0v; v0.y += m1v;
                v1.x += m0v; v1.y += m1v;
            }
            *(float2*)(C + (size_t)r0 * NDIM + cc)       = v0;
            *(float2*)(C + (size_t)(r0 + 8) * NDIM + cc) = v1;
        }
    }
}

// ======================= GEMM3: plane-fed, 1-term, LDG.128 producer ========
// SMEM: A-hi plane at 0, B-hi plane at 6144; slot = 12288 B, 2 slots.
#define SLOT3 12288
static constexpr int SMEM3_BYTES = 2 * SLOT3;   // 24576

__global__ __launch_bounds__(128) void gemm3_kernel(
    const __half* __restrict__ Ah, const __half* __restrict__ Bh,
    float* __restrict__ C)
{
    extern __shared__ __align__(16) char smem[];
    const int tid = threadIdx.x, wid = tid >> 5, lid = tid & 31;
    const int g = lid >> 2, tg = lid & 3;
    const int wm = (wid >> 1) * 64, wn = (wid & 1) * 64;
    const int M0 = blockIdx.y * 128, N0 = blockIdx.x * 128;
    const size_t b = blockIdx.z;
    Ah += b * 1048576ull; Bh += b * 1048576ull; C += b * 1048576ull;

    // producer: 2 threads per row, one uint4 (16B = 8 halves) each; 2 row passes
    const int r2 = tid >> 1;            // 0..63 (+64 per pass)
    const int qh = (tid & 1) * 8;       // halves sub-offset in the 16-half slice
    const __half* Ag = Ah + (size_t)(M0 + r2) * NDIM + qh;
    const __half* Bg = Bh + (size_t)(N0 + r2) * NDIM + qh;

    float acc[4][8][4];
    #pragma unroll
    for (int mi = 0; mi < 4; mi++)
        #pragma unroll
        for (int ni = 0; ni < 8; ni++)
            #pragma unroll
            for (int v = 0; v < 4; v++) acc[mi][ni][v] = 0.0f;

    uint4 bufA[2], bufB[2];

    auto ldg = [&](int c) {
        const int k0 = c << 4;
        #pragma unroll
        for (int p = 0; p < 2; p++) {
            bufA[p] = *(const uint4*)(Ag + (size_t)64 * p * NDIM + k0);
            bufB[p] = *(const uint4*)(Bg + (size_t)64 * p * NDIM + k0);
        }
    };

    auto sts = [&](int slot) {
        char* base = smem + slot * SLOT3;
        #pragma unroll
        for (int p = 0; p < 2; p++) {
            const int ro = (r2 + 64 * p) * ROWB + qh * 2;
            *(uint4*)(base + ro)        = bufA[p];
            *(uint4*)(base + 6144 + ro) = bufB[p];
        }
    };

    auto frag_mma = [&](int slot) {
        const char* base = smem + slot * SLOT3;
        uint32_t bh[8][2];
        #pragma unroll
        for (int ni = 0; ni < 8; ni++) {
            const int n0 = (wn + ni * 8 + g) * ROWB + tg * 4;
            bh[ni][0] = *(const uint32_t*)(base + 6144 + n0);
            bh[ni][1] = *(const uint32_t*)(base + 6144 + n0 + 16);
        }
        #pragma unroll
        for (int mi = 0; mi < 4; mi++) {
            const int r0 = (wm + mi * 16 + g) * ROWB + tg * 4;
            const int r1 = r0 + 8 * ROWB;
            uint32_t ah[4];
            ah[0] = *(const uint32_t*)(base + r0);
            ah[1] = *(const uint32_t*)(base + r1);
            ah[2] = *(const uint32_t*)(base + r0 + 16);
            ah[3] = *(const uint32_t*)(base + r1 + 16);
            #pragma unroll
            for (int ni = 0; ni < 8; ni++)
                mma16(acc[mi][ni], ah, bh[ni]);
        }
    };

    ldg(0);
    sts(0);
    __syncthreads();
    for (int c = 0; c < 64; c++) {
        if (c + 1 < 64) ldg(c + 1);
        frag_mma(c & 1);
        if (c + 1 < 64) sts((c + 1) & 1);
        __syncthreads();
    }

    #pragma unroll
    for (int mi = 0; mi < 4; mi++) {
        #pragma unroll
        for (int ni = 0; ni < 8; ni++) {
            const int r0 = M0 + wm + mi * 16 + g;
            const int cc = N0 + wn + ni * 8 + 2 * tg;
            *(float2*)(C + (size_t)r0 * NDIM + cc) =
                make_float2(acc[mi][ni][0], acc[mi][ni][1]);
            *(float2*)(C + (size_t)(r0 + 8) * NDIM + cc) =
                make_float2(acc[mi][ni][2], acc[mi][ni][3]);
        }
    }
}

// 1024x1024 f32 transpose (W), block (32,8)
__global__ __launch_bounds__(256) void transpose_kernel(const float* __restrict__ src,
                                                        float* __restrict__ dst)
{
    __shared__ float t[32][33];
    const int bx = blockIdx.x * 32, by = blockIdx.y * 32;
    const int x = threadIdx.x, y4 = threadIdx.y * 4;
    #pragma unroll
    for (int i = 0; i < 4; i++)
        t[y4 + i][x] = src[(size_t)(by + y4 + i) * 1024 + bx + x];
    __syncthreads();
    #pragma unroll
    for (int i = 0; i < 4; i++)
        dst[(size_t)(bx + y4 + i) * 1024 + by + x] = t[x][y4 + i];
}

// 1024x1024 transpose -> f16 plane (values), per blockIdx.z slice
__global__ __launch_bounds__(256) void transpose_h_kernel(const float* __restrict__ src,
                                                          __half* __restrict__ dh)
{
    __shared__ float t[32][33];
    const size_t b = blockIdx.z;
    src += b * 1048576ull;
    dh  += b * 1048576ull;
    const int bx = blockIdx.x * 32, by = blockIdx.y * 32;
    const int x = threadIdx.x, y4 = threadIdx.y * 4;
    #pragma unroll
    for (int i = 0; i < 4; i++)
        t[y4 + i][x] = src[(size_t)(by + y4 + i) * 1024 + bx + x];
    __syncthreads();
    #pragma unroll
    for (int i = 0; i < 4; i++)
        dh[(size_t)(bx + y4 + i) * 1024 + by + x] = __float2half_rn(t[x][y4 + i]);
}

// In-place row softmax, row length 1024; emits f16 score plane
__global__ __launch_bounds__(256) void softmax_kernel(float* __restrict__ S,
                                                      __half* __restrict__ Sh)
{
    __shared__ float red[8];
    size_t row = blockIdx.x;
    float4* p = reinterpret_cast<float4*>(S + row * 1024);
    int t = threadIdx.x;

    float4 v = p[t];
    float m = fmaxf(fmaxf(v.x, v.y), fmaxf(v.z, v.w));
    #pragma unroll
    for (int o = 16; o; o >>= 1) m = fmaxf(m, __shfl_xor_sync(0xffffffffu, m, o));
    if ((t & 31) == 0) red[t >> 5] = m;
    __syncthreads();
    m = red[0];
    #pragma unroll
    for (int i = 1; i < 8; i++) m = fmaxf(m, red[i]);

    v.x = expf(v.x - m); v.y = expf(v.y - m);
    v.z = expf(v.z - m); v.w = expf(v.w - m);
    float s = v.x + v.y + v.z + v.w;
    #pragma unroll
    for (int o = 16; o; o >>= 1) s += __shfl_xor_sync(0xffffffffu, s, o);
    __syncthreads();
    if ((t & 31) == 0) red[t >> 5] = s;
    __syncthreads();
    s = red[0];
    #pragma unroll
    for (int i = 1; i < 8; i++) s += red[i];

    float inv = 1.0f / s;
    v.x *= inv; v.y *= inv; v.z *= inv; v.w *= inv;
    p[t] = v;

    uint32_t h0 = pack_h2(v.x, v.y), h1 = pack_h2(v.z, v.w);
    *(uint2*)(Sh + row * 1024 + 4 * t) = make_uint2(h0, h1);
}

extern "C" void kernel_launch(void* const* d_in, const int* in_sizes, int n_in,
                              void* d_out, int out_size)
{
    (void)in_sizes; (void)n_in; (void)out_size;
    const float* query  = (const float*)d_in[0];   // [16,1024,1024]
    const float* keys   = (const float*)d_in[1];   // [16,1024,1024]
    const float* values = (const float*)d_in[2];   // [16,1024,1024]
    const float* W      = (const float*)d_in[3];   // [1024,1024]
    const float* mask   = (const float*)d_in[4];   // [16,1024]

    float* score = (float*)d_out;                        // [16,1024,1024]
    float* ctx   = score + (size_t)16 * 1024 * 1024;     // [16,1024,1024]

    cudaFuncSetAttribute(gemm_fp16_kernel<false, 3>,
                         cudaFuncAttributeMaxDynamicSharedMemorySize, SMEM_BYTES);
    cudaFuncSetAttribute(gemm_fp16_kernel<true, 3>,
                         cudaFuncAttributeMaxDynamicSharedMemorySize, SMEM_BYTES);
    cudaFuncSetAttribute(gemm3_kernel,
                         cudaFuncAttributeMaxDynamicSharedMemorySize, SMEM3_BYTES);

    float* qW;    cudaGetSymbolAddress((void**)&qW,   g_qW);
    float* Wt;    cudaGetSymbolAddress((void**)&Wt,   g_Wt);
    __half *valh, *sch;
    cudaGetSymbolAddress((void**)&valh, g_valh);
    cudaGetSymbolAddress((void**)&sch,  g_sch);

    // Prep: W^T (f32, as R8) and values^T straight to f16
    transpose_kernel<<<dim3(32, 32, 1),  dim3(32, 8)>>>(W, Wt);
    transpose_h_kernel<<<dim3(32, 32, 16), dim3(32, 8)>>>(values, valh);

    // qW = query @ W : one 16384x1024x1024 NT GEMM (W batch-shared), 3-term (R8)
    gemm_fp16_kernel<false, 3><<<dim3(8, 128, 1), 128, SMEM_BYTES>>>(
        query, Wt, qW, nullptr, 0, 0, 0);

    // logits = qW @ keys^T + mask -> score (NT), 3-term (R8)
    gemm_fp16_kernel<true, 3><<<dim3(8, 8, 16), 128, SMEM_BYTES>>>(
        qW, keys, score, mask, 1048576, 1048576, 1048576);

    // softmax in place; emit f16 score plane
    softmax_kernel<<<16384, 256>>>(score, sch);

    // ctx = score @ values : plane-fed 1-term fp16 (pure-copy LDG.128 producer)
    gemm3_kernel<<<dim3(8, 8, 16), 128, SMEM3_BYTES>>>(sch, valh, ctx);
}